// round 7
// baseline (speedup 1.0000x reference)
#include <cuda_runtime.h>
#include <cstdint>

#define H 224
#define W 224
#define NPIX (H * W)          // 50176
#define NIMG 256
#define K2_THREADS 1024
#define HIST_WORDS 16384      // 65536 u8 bins packed 4-per-u32 = 64 KB

// ---------------- scratch (no allocations allowed) ----------------
__device__ unsigned char g_buf[(size_t)NIMG * NPIX + 64];
__device__ unsigned int  d_sum8[NIMG * 8];
__device__ unsigned int  d_sumsq8[NIMG * 8];
__device__ float         d_feat[NIMG * 4 * 4];   // [n][offset][con,dis,hom,asm]
// 64 MB global partial histogram (u8-packed). Zero-initialized at module load;
// every K2 CTA re-zeroes its own region after consuming it, so each replay
// (and the first correctness call) sees zeros.
__device__ unsigned int  g_hist[(size_t)NIMG * 4 * HIST_WORDS];

// ---------------- Kernel 1: quantize + moments (8 CTAs per image) ----------------
__global__ __launch_bounds__(256) void quantize_kernel(const float* __restrict__ x) {
    const int n = blockIdx.x >> 3;       // image index = b*16 + f
    const int q = blockIdx.x & 7;        // eighth
    const int b = n >> 4, f = n & 15;
    const size_t base = (size_t)(b * 48 + f) * NPIX;
    const float4* __restrict__ x0 = (const float4*)(x + base);
    const float4* __restrict__ x1 = (const float4*)(x + base + (size_t)16 * NPIX);
    const float4* __restrict__ x2 = (const float4*)(x + base + (size_t)32 * NPIX);
    unsigned int* __restrict__ gout = (unsigned int*)(g_buf + (size_t)n * NPIX);

    const int v0 = q * (NPIX / 32);      // 12544 float4 words total / 8 = 1568
    const int v1 = v0 + (NPIX / 32);

    unsigned int s = 0, qq = 0;
    for (int v = v0 + threadIdx.x; v < v1; v += 256) {
        float4 p0 = x0[v], p1 = x1[v], p2 = x2[v];
        // match jnp.mean -> sum/3, then *255, floor (no FMA/reassociation)
        int g0 = (int)__fmul_rn(__fdiv_rn(__fadd_rn(__fadd_rn(p0.x, p1.x), p2.x), 3.0f), 255.0f);
        int g1 = (int)__fmul_rn(__fdiv_rn(__fadd_rn(__fadd_rn(p0.y, p1.y), p2.y), 3.0f), 255.0f);
        int g2 = (int)__fmul_rn(__fdiv_rn(__fadd_rn(__fadd_rn(p0.z, p1.z), p2.z), 3.0f), 255.0f);
        int g3 = (int)__fmul_rn(__fdiv_rn(__fadd_rn(__fadd_rn(p0.w, p1.w), p2.w), 3.0f), 255.0f);
        s  += (unsigned)(g0 + g1 + g2 + g3);
        qq += (unsigned)(g0 * g0 + g1 * g1 + g2 * g2 + g3 * g3);
        gout[v] = (unsigned)g0 | ((unsigned)g1 << 8) | ((unsigned)g2 << 16) | ((unsigned)g3 << 24);
    }
    // block reduction (exact, u32)
    s  = __reduce_add_sync(0xFFFFFFFFu, s);
    qq = __reduce_add_sync(0xFFFFFFFFu, qq);
    __shared__ unsigned int ss[8], sq[8];
    const int warp = threadIdx.x >> 5, lane = threadIdx.x & 31;
    if (lane == 0) { ss[warp] = s; sq[warp] = qq; }
    __syncthreads();
    if (threadIdx.x == 0) {
        unsigned int ts = 0, tq = 0;
        #pragma unroll
        for (int i = 0; i < 8; i++) { ts += ss[i]; tq += sq[i]; }
        d_sum8[blockIdx.x] = ts; d_sumsq8[blockIdx.x] = tq;
    }
}

// ---------------- Kernel 2: per-(image,offset) GLCM ----------------
// Pair phase splits increments 12:4 between smem ATOMS and global REDG
// (separate HW accept queues), then merges + self-zeroes the global part.
template <int DR, int DC>
__device__ __forceinline__ void glcm_body(int n, int out_idx, unsigned int* hist) {
    constexpr int A0 = (DC < 0) ? 1 : 0;     // a-column shift
    constexpr int B0 = (DC > 0) ? 1 : 0;     // b-column shift
    constexpr int R  = H - DR;
    constexpr int C2 = W - ((DC < 0) ? -DC : DC);
    constexpr int CHUNKS = 14;               // 14*16 = 224 columns per row
    constexpr float NP = (float)(R * C2);

    const unsigned char* __restrict__ g = g_buf + (size_t)n * NPIX;
    unsigned int* __restrict__ gh = g_hist + (size_t)out_idx * HIST_WORDS;
    const int tid = threadIdx.x;

    // zero 64 KB smem histogram (uint4 stores)
    {
        uint4 z = make_uint4(0u, 0u, 0u, 0u);
        uint4* h4 = (uint4*)hist;
        #pragma unroll
        for (int i = tid; i < HIST_WORDS / 4; i += K2_THREADS) h4[i] = z;
    }
    __syncthreads();

    // ---- pair accumulation: 16 pairs/iter ----
    const int total = R * CHUNKS;
    for (int m = tid; m < total; m += K2_THREADS) {
        const int r = m / CHUNKS;
        const int k = m - r * CHUNKS;
        // mask for the single possibly-invalid pair (w=3,p=3) this iteration:
        // for C2==223 offsets, column 223 (k==13) must contribute 0.
        const unsigned int lastmask = (C2 == W || k != 13) ? 0xFFFFFFFFu : 0u;

        const unsigned int* rowa = (const unsigned int*)(g + r * W);
        const unsigned int* rowb = (const unsigned int*)(g + (r + DR) * W);
        uint4 av = ((const uint4*)rowa)[k];
        uint4 bv = ((const uint4*)rowb)[k];
        unsigned int A[5] = { av.x, av.y, av.z, av.w, 0u };
        unsigned int B[5] = { bv.x, bv.y, bv.z, bv.w, 0u };
        if (A0) A[4] = rowa[k * 4 + 4];      // padded buffer: safe at row/image end
        if (B0) B[4] = rowb[k * 4 + 4];
        unsigned int aw[4], bw[4];
        #pragma unroll
        for (int w = 0; w < 4; w++) {
            aw[w] = A0 ? __funnelshift_r(A[w], A[w + 1], 8) : A[w];
            bw[w] = B0 ? __funnelshift_r(B[w], B[w + 1], 8) : B[w];
        }
        #pragma unroll
        for (int w = 0; w < 4; w++) {
            #pragma unroll
            for (int p = 0; p < 4; p++) {
                // single-PRMT byte extraction
                unsigned int a = __byte_perm(aw[w], 0u, 0x4440u + (unsigned)p);
                unsigned int b = __byte_perm(bw[w], 0u, 0x4440u + (unsigned)p);
                // swizzled u8 bin layout: slot(i,j) = i*256 + ((j + 4i) & 255)
                unsigned int t = b + 4u * a;
                unsigned int woff = (a << 8) | (t & 252u);        // byte offset of u32 word
                // val = 1 << (8*(b&3))
                unsigned int val = __funnelshift_l(0u, 1u, b << 3);
                if (w == 3 && p == 3) val &= lastmask;            // kill the invalid pair
                if (p == 3) {
                    // 4/16 pairs -> global reduction path (no return => RED)
                    atomicAdd((unsigned int*)((char*)gh + woff), val);
                } else {
                    atomicAdd((unsigned int*)((char*)hist + woff), val);
                }
            }
        }
    }
    __threadfence();          // make this thread's REDs visible chip-wide
    __syncthreads();

    // ---- merge global partial into smem, self-zero global region ----
    {
        uint4* h4 = (uint4*)hist;
        uint4* g4 = (uint4*)gh;
        const uint4 z = make_uint4(0u, 0u, 0u, 0u);
        #pragma unroll
        for (int i = tid; i < HIST_WORDS / 4; i += K2_THREADS) {
            uint4 gv = __ldcg((const uint4*)&g4[i]);   // bypass L1
            uint4 hv = h4[i];
            hv.x += gv.x; hv.y += gv.y; hv.z += gv.z; hv.w += gv.w;  // packed, no carry
            h4[i] = hv;
            g4[i] = z;                                  // clean for next replay
        }
    }
    __syncthreads();

    // ---- stats over 64K bins (swizzle makes transpose read conflict-free) ----
    float s2 = 0.f, scon = 0.f, sdis = 0.f, shom = 0.f;
    #pragma unroll 4
    for (int it = 0; it < 65536 / K2_THREADS; ++it) {
        const int l = tid + (it << 10);
        const int i = l >> 8, j = l & 255;
        const unsigned int slot1 = (unsigned)((i << 8) | ((j + 4 * i) & 255));
        const unsigned int c1 = (hist[slot1 >> 2] >> ((slot1 & 3u) << 3)) & 255u;
        const unsigned int slot2 = (unsigned)((j << 8) | ((i + 4 * j) & 255));
        const unsigned int c2 = (hist[slot2 >> 2] >> ((slot2 & 3u) << 3)) & 255u;
        const float cs = (float)(c1 + c2);
        s2 += cs * cs;
        const float d  = (float)(i - j);
        const float d2 = d * d;
        const float cf = (float)c1;
        scon += cf * d2;
        sdis += cf * fabsf(d);
        shom += cf / (1.0f + d2);
    }

    // deterministic block reduction
    __shared__ float red[4][32];
    float v0 = s2, v1 = scon, v2 = sdis, v3 = shom;
    #pragma unroll
    for (int off = 16; off; off >>= 1) {
        v0 += __shfl_xor_sync(0xFFFFFFFFu, v0, off);
        v1 += __shfl_xor_sync(0xFFFFFFFFu, v1, off);
        v2 += __shfl_xor_sync(0xFFFFFFFFu, v2, off);
        v3 += __shfl_xor_sync(0xFFFFFFFFu, v3, off);
    }
    const int warp = tid >> 5, lane = tid & 31;
    if (lane == 0) { red[0][warp] = v0; red[1][warp] = v1; red[2][warp] = v2; red[3][warp] = v3; }
    __syncthreads();
    if (tid < 32) {
        float a0 = red[0][tid], a1 = red[1][tid], a2 = red[2][tid], a3 = red[3][tid];
        #pragma unroll
        for (int off = 16; off; off >>= 1) {
            a0 += __shfl_xor_sync(0xFFFFFFFFu, a0, off);
            a1 += __shfl_xor_sync(0xFFFFFFFFu, a1, off);
            a2 += __shfl_xor_sync(0xFFFFFFFFu, a2, off);
            a3 += __shfl_xor_sync(0xFFFFFFFFu, a3, off);
        }
        if (tid == 0) {
            d_feat[out_idx * 4 + 0] = a1 / NP;                   // contrast
            d_feat[out_idx * 4 + 1] = a2 / NP;                   // dissimilarity
            d_feat[out_idx * 4 + 2] = a3 / NP;                   // homogeneity
            d_feat[out_idx * 4 + 3] = a0 / (4.0f * NP * NP);     // ASM
        }
    }
}

__global__ __launch_bounds__(K2_THREADS, 2) void glcm_kernel() {
    extern __shared__ unsigned int hist[];
    const int bx = blockIdx.x;
    const int n = bx >> 2;
    const int o = bx & 3;
    switch (o) {
        case 0: glcm_body<0, 1>(n, bx, hist); break;   // (0,1)
        case 1: glcm_body<1, 1>(n, bx, hist); break;   // (1,1)
        case 2: glcm_body<1, 0>(n, bx, hist); break;   // (1,0)
        default: glcm_body<1, -1>(n, bx, hist); break; // (1,-1)
    }
}

// ---------------- Kernel 3: finalize ----------------
__global__ __launch_bounds__(256) void finalize_kernel(float* __restrict__ out) {
    const int n = threadIdx.x;
    unsigned int tsum = 0, tsq = 0;
    #pragma unroll
    for (int q = 0; q < 8; q++) { tsum += d_sum8[n * 8 + q]; tsq += d_sumsq8[n * 8 + q]; }
    const double inv = 1.0 / (double)NPIX;
    const double mean = (double)tsum * inv;
    double var = (double)tsq * inv - mean * mean;
    if (var < 0.0) var = 0.0;
    float con = 0.f, dis = 0.f, hom = 0.f, as = 0.f;
    #pragma unroll
    for (int o = 0; o < 4; o++) {
        const float* f4 = &d_feat[(n * 4 + o) * 4];
        con += f4[0]; dis += f4[1]; hom += f4[2]; as += f4[3];
    }
    con *= 0.25f; dis *= 0.25f; hom *= 0.25f; as *= 0.25f;
    float* o6 = out + n * 6;
    o6[0] = (float)sqrt(var);
    o6[1] = con;
    o6[2] = dis;
    o6[3] = hom;
    o6[4] = as;
    o6[5] = sqrtf(as);
}

// ---------------- launch ----------------
extern "C" void kernel_launch(void* const* d_in, const int* in_sizes, int n_in,
                              void* d_out, int out_size) {
    (void)in_sizes; (void)n_in; (void)out_size;
    const float* x = (const float*)d_in[0];
    float* out = (float*)d_out;

    cudaFuncSetAttribute(glcm_kernel, cudaFuncAttributeMaxDynamicSharedMemorySize,
                         HIST_WORDS * sizeof(unsigned int));

    quantize_kernel<<<NIMG * 8, 256>>>(x);
    glcm_kernel<<<NIMG * 4, K2_THREADS, HIST_WORDS * sizeof(unsigned int)>>>();
    finalize_kernel<<<1, 256>>>(out);
}

// round 8
// speedup vs baseline: 1.3118x; 1.3118x over previous
#include <cuda_runtime.h>
#include <cstdint>

#define H 224
#define W 224
#define NPIX (H * W)          // 50176
#define NIMG 256
#define K2_THREADS 1024
#define K2_BLOCKS (NIMG * 4)
#define HIST_WORDS 16384      // 65536 u8 bins packed 4-per-u32 = 64 KB

// ---------------- scratch (no allocations allowed) ----------------
__device__ unsigned char g_buf[(size_t)NIMG * NPIX + 64];
__device__ unsigned int  d_sum8[NIMG * 8];
__device__ unsigned int  d_sumsq8[NIMG * 8];
__device__ float         d_feat[NIMG * 4 * 4];   // [n][offset][con,dis,hom,asm]
__device__ unsigned int  d_ticket;               // last-CTA election; reset to 0 each run

// ---------------- Kernel 1: quantize + moments ----------------
// grid = 1024 CTAs, each processes 2 of the 2048 (image, eighth) work items:
// all CTAs resident in one wave -> no wave tail.
__global__ __launch_bounds__(256) void quantize_kernel(const float* __restrict__ x) {
    for (int item = blockIdx.x; item < NIMG * 8; item += gridDim.x) {
        const int n = item >> 3;         // image index = b*16 + f
        const int q = item & 7;          // eighth
        const int b = n >> 4, f = n & 15;
        const size_t base = (size_t)(b * 48 + f) * NPIX;
        const float4* __restrict__ x0 = (const float4*)(x + base);
        const float4* __restrict__ x1 = (const float4*)(x + base + (size_t)16 * NPIX);
        const float4* __restrict__ x2 = (const float4*)(x + base + (size_t)32 * NPIX);
        unsigned int* __restrict__ gout = (unsigned int*)(g_buf + (size_t)n * NPIX);

        const int v0 = q * (NPIX / 32);  // 12544 float4 words / 8 = 1568 per item
        const int v1 = v0 + (NPIX / 32);

        unsigned int s = 0, qq = 0;
        for (int v = v0 + threadIdx.x; v < v1; v += 256) {
            float4 p0 = x0[v], p1 = x1[v], p2 = x2[v];
            // match jnp.mean -> sum/3, then *255, floor (no FMA/reassociation)
            int g0 = (int)__fmul_rn(__fdiv_rn(__fadd_rn(__fadd_rn(p0.x, p1.x), p2.x), 3.0f), 255.0f);
            int g1 = (int)__fmul_rn(__fdiv_rn(__fadd_rn(__fadd_rn(p0.y, p1.y), p2.y), 3.0f), 255.0f);
            int g2 = (int)__fmul_rn(__fdiv_rn(__fadd_rn(__fadd_rn(p0.z, p1.z), p2.z), 3.0f), 255.0f);
            int g3 = (int)__fmul_rn(__fdiv_rn(__fadd_rn(__fadd_rn(p0.w, p1.w), p2.w), 3.0f), 255.0f);
            s  += (unsigned)(g0 + g1 + g2 + g3);
            qq += (unsigned)(g0 * g0 + g1 * g1 + g2 * g2 + g3 * g3);
            gout[v] = (unsigned)g0 | ((unsigned)g1 << 8) | ((unsigned)g2 << 16) | ((unsigned)g3 << 24);
        }
        // block reduction (exact, u32)
        s  = __reduce_add_sync(0xFFFFFFFFu, s);
        qq = __reduce_add_sync(0xFFFFFFFFu, qq);
        __shared__ unsigned int ss[8], sq[8];
        const int warp = threadIdx.x >> 5, lane = threadIdx.x & 31;
        if (lane == 0) { ss[warp] = s; sq[warp] = qq; }
        __syncthreads();
        if (threadIdx.x == 0) {
            unsigned int ts = 0, tq = 0;
            #pragma unroll
            for (int i = 0; i < 8; i++) { ts += ss[i]; tq += sq[i]; }
            d_sum8[item] = ts; d_sumsq8[item] = tq;
        }
        __syncthreads();   // ss/sq reuse across items
    }
}

// ---------------- Kernel 2: per-(image,offset) GLCM, u8 smem histogram ----------------
template <int DR, int DC>
__device__ __forceinline__ void glcm_body(int n, int out_idx, unsigned int* hist) {
    constexpr int A0 = (DC < 0) ? 1 : 0;     // a-column shift
    constexpr int B0 = (DC > 0) ? 1 : 0;     // b-column shift
    constexpr int R  = H - DR;
    constexpr int C2 = W - ((DC < 0) ? -DC : DC);
    constexpr int CHUNKS = 14;               // 14*16 = 224 columns per row
    constexpr float NP = (float)(R * C2);

    const unsigned char* __restrict__ g = g_buf + (size_t)n * NPIX;
    const int tid = threadIdx.x;

    // zero 64 KB histogram (uint4 stores)
    {
        uint4 z = make_uint4(0u, 0u, 0u, 0u);
        uint4* h4 = (uint4*)hist;
        #pragma unroll
        for (int i = tid; i < HIST_WORDS / 4; i += K2_THREADS) h4[i] = z;
    }
    __syncthreads();

    // ---- pair accumulation: 16 pairs/iter, no per-pair predicates ----
    const int total = R * CHUNKS;
    for (int m = tid; m < total; m += K2_THREADS) {
        const int r = m / CHUNKS;
        const int k = m - r * CHUNKS;
        // only pair (w=3,p=3) can be out of range (column 223 when k==13, C2==223)
        const unsigned int lastmask = (C2 == W || k != 13) ? 0xFFFFFFFFu : 0u;

        const unsigned int* rowa = (const unsigned int*)(g + r * W);
        const unsigned int* rowb = (const unsigned int*)(g + (r + DR) * W);
        uint4 av = ((const uint4*)rowa)[k];
        uint4 bv = ((const uint4*)rowb)[k];
        unsigned int A[5] = { av.x, av.y, av.z, av.w, 0u };
        unsigned int B[5] = { bv.x, bv.y, bv.z, bv.w, 0u };
        if (A0) A[4] = rowa[k * 4 + 4];      // padded buffer: safe at row/image end
        if (B0) B[4] = rowb[k * 4 + 4];
        unsigned int aw[4], bw[4];
        #pragma unroll
        for (int w = 0; w < 4; w++) {
            aw[w] = A0 ? __funnelshift_r(A[w], A[w + 1], 8) : A[w];
            bw[w] = B0 ? __funnelshift_r(B[w], B[w + 1], 8) : B[w];
        }
        #pragma unroll
        for (int w = 0; w < 4; w++) {
            #pragma unroll
            for (int p = 0; p < 4; p++) {
                unsigned int a = __byte_perm(aw[w], 0u, 0x4440u + (unsigned)p);
                unsigned int b = __byte_perm(bw[w], 0u, 0x4440u + (unsigned)p);
                // swizzled u8 bin layout: slot(i,j) = i*256 + ((j + 4i) & 255)
                unsigned int t = b + 4u * a;
                unsigned int woff = (a << 8) | (t & 252u);        // byte offset of u32 word
                unsigned int val = __funnelshift_l(0u, 1u, b << 3); // 1 << (8*(b&3))
                if (w == 3 && p == 3) val &= lastmask;
                atomicAdd((unsigned int*)((char*)hist + woff), val);
            }
        }
    }
    __syncthreads();

    // ---- stats over 64K bins (swizzle makes transpose read conflict-free) ----
    float s2 = 0.f, scon = 0.f, sdis = 0.f, shom = 0.f;
    #pragma unroll 4
    for (int it = 0; it < 65536 / K2_THREADS; ++it) {
        const int l = tid + (it << 10);
        const int i = l >> 8, j = l & 255;
        const unsigned int slot1 = (unsigned)((i << 8) | ((j + 4 * i) & 255));
        const unsigned int c1 = (hist[slot1 >> 2] >> ((slot1 & 3u) << 3)) & 255u;
        const unsigned int slot2 = (unsigned)((j << 8) | ((i + 4 * j) & 255));
        const unsigned int c2 = (hist[slot2 >> 2] >> ((slot2 & 3u) << 3)) & 255u;
        const float cs = (float)(c1 + c2);
        s2 += cs * cs;
        const float d  = (float)(i - j);
        const float d2 = d * d;
        const float cf = (float)c1;
        scon += cf * d2;
        sdis += cf * fabsf(d);
        shom += cf / (1.0f + d2);
    }

    // deterministic block reduction
    __shared__ float red[4][32];
    float v0 = s2, v1 = scon, v2 = sdis, v3 = shom;
    #pragma unroll
    for (int off = 16; off; off >>= 1) {
        v0 += __shfl_xor_sync(0xFFFFFFFFu, v0, off);
        v1 += __shfl_xor_sync(0xFFFFFFFFu, v1, off);
        v2 += __shfl_xor_sync(0xFFFFFFFFu, v2, off);
        v3 += __shfl_xor_sync(0xFFFFFFFFu, v3, off);
    }
    const int warp = tid >> 5, lane = tid & 31;
    if (lane == 0) { red[0][warp] = v0; red[1][warp] = v1; red[2][warp] = v2; red[3][warp] = v3; }
    __syncthreads();
    if (tid < 32) {
        float a0 = red[0][tid], a1 = red[1][tid], a2 = red[2][tid], a3 = red[3][tid];
        #pragma unroll
        for (int off = 16; off; off >>= 1) {
            a0 += __shfl_xor_sync(0xFFFFFFFFu, a0, off);
            a1 += __shfl_xor_sync(0xFFFFFFFFu, a1, off);
            a2 += __shfl_xor_sync(0xFFFFFFFFu, a2, off);
            a3 += __shfl_xor_sync(0xFFFFFFFFu, a3, off);
        }
        if (tid == 0) {
            d_feat[out_idx * 4 + 0] = a1 / NP;                   // contrast
            d_feat[out_idx * 4 + 1] = a2 / NP;                   // dissimilarity
            d_feat[out_idx * 4 + 2] = a3 / NP;                   // homogeneity
            d_feat[out_idx * 4 + 3] = a0 / (4.0f * NP * NP);     // ASM
        }
    }
}

// fused finalize: executed by the last CTA to finish (threadFenceReduction pattern)
__device__ __forceinline__ void finalize_body(float* __restrict__ out) {
    const int n = threadIdx.x;
    if (n >= NIMG) return;
    unsigned int tsum = 0, tsq = 0;
    #pragma unroll
    for (int q = 0; q < 8; q++) { tsum += d_sum8[n * 8 + q]; tsq += d_sumsq8[n * 8 + q]; }
    const double inv = 1.0 / (double)NPIX;
    const double mean = (double)tsum * inv;
    double var = (double)tsq * inv - mean * mean;
    if (var < 0.0) var = 0.0;
    float con = 0.f, dis = 0.f, hom = 0.f, as = 0.f;
    #pragma unroll
    for (int o = 0; o < 4; o++) {
        const float* f4 = &d_feat[(n * 4 + o) * 4];
        con += f4[0]; dis += f4[1]; hom += f4[2]; as += f4[3];
    }
    con *= 0.25f; dis *= 0.25f; hom *= 0.25f; as *= 0.25f;
    float* o6 = out + n * 6;
    o6[0] = (float)sqrt(var);
    o6[1] = con;
    o6[2] = dis;
    o6[3] = hom;
    o6[4] = as;
    o6[5] = sqrtf(as);
}

__global__ __launch_bounds__(K2_THREADS, 2) void glcm_kernel(float* __restrict__ out) {
    extern __shared__ unsigned int hist[];
    const int bx = blockIdx.x;
    const int n = bx >> 2;
    const int o = bx & 3;
    switch (o) {
        case 0: glcm_body<0, 1>(n, bx, hist); break;   // (0,1)
        case 1: glcm_body<1, 1>(n, bx, hist); break;   // (1,1)
        case 2: glcm_body<1, 0>(n, bx, hist); break;   // (1,0)
        default: glcm_body<1, -1>(n, bx, hist); break; // (1,-1)
    }

    // ---- last-CTA finalize ----
    __shared__ unsigned int is_last;
    __syncthreads();                      // d_feat write (tid 0) done
    if (threadIdx.x == 0) {
        __threadfence();                  // publish d_feat before ticket
        is_last = (atomicAdd(&d_ticket, 1u) == K2_BLOCKS - 1u) ? 1u : 0u;
    }
    __syncthreads();
    if (is_last) {
        __threadfence();                  // acquire all CTAs' d_feat writes
        finalize_body(out);
        if (threadIdx.x == 0) d_ticket = 0u;   // reset for next replay
    }
}

// ---------------- launch ----------------
extern "C" void kernel_launch(void* const* d_in, const int* in_sizes, int n_in,
                              void* d_out, int out_size) {
    (void)in_sizes; (void)n_in; (void)out_size;
    const float* x = (const float*)d_in[0];
    float* out = (float*)d_out;

    cudaFuncSetAttribute(glcm_kernel, cudaFuncAttributeMaxDynamicSharedMemorySize,
                         HIST_WORDS * sizeof(unsigned int));

    quantize_kernel<<<1024, 256>>>(x);
    glcm_kernel<<<K2_BLOCKS, K2_THREADS, HIST_WORDS * sizeof(unsigned int)>>>(out);
}

// round 9
// speedup vs baseline: 1.3928x; 1.0617x over previous
#include <cuda_runtime.h>
#include <cstdint>

#define H 224
#define W 224
#define NPIX (H * W)          // 50176
#define NIMG 256
#define WPR 60                // words per padded row (56 data + 4 pad)
#define V4PR 15               // uint4 per padded row
#define K2_THREADS 512
#define K2_BLOCKS (NIMG * 4)
#define HIST_WORDS 16384      // 65536 u8 bins packed 4-per-u32 = 64 KB

// ---------------- scratch (no allocations allowed) ----------------
__device__ uint4         g_buf4[(size_t)NIMG * 224 * V4PR];   // padded gray images
__device__ unsigned int  d_sum[NIMG];     // accumulated; K3 resets after reading
__device__ unsigned int  d_sumsq[NIMG];
__device__ float         d_feat[NIMG * 4 * 4];   // [n][offset][con,dis,hom,asm]

// ---------------- Kernel 1: quantize + moments ----------------
// 8192 items (1/32 image = 7 rows each); grid 1184 = one resident wave.
__global__ __launch_bounds__(256) void quantize_kernel(const float* __restrict__ x) {
    __shared__ unsigned int ss[8], sq[8];
    for (int item = blockIdx.x; item < NIMG * 32; item += gridDim.x) {
        const int n = item >> 5, seg = item & 31;
        const int b = n >> 4, f = n & 15;
        const float4* __restrict__ xb = (const float4*)x + (size_t)(b * 48 + f) * 12544;
        unsigned int* __restrict__ gw =
            (unsigned int*)g_buf4 + (size_t)n * (224 * WPR) + seg * 7 * WPR;
        const int rbase = seg * 7;

        unsigned int s = 0, q = 0;
        for (int widx = threadIdx.x; widx < 7 * WPR; widx += 256) {
            const int row = widx / WPR;
            const int cw  = widx - row * WPR;
            if (cw >= 56) {
                gw[widx] = 0xFFFFFFFFu;   // poison pad (bin 255 never natural)
            } else {
                const int wsrc = (rbase + row) * 56 + cw;
                float4 p0 = xb[wsrc];
                float4 p1 = xb[wsrc + 16 * 12544];
                float4 p2 = xb[wsrc + 32 * 12544];
                // match jnp.mean -> sum/3, then *255, floor (no FMA/reassociation)
                int g0 = (int)__fmul_rn(__fdiv_rn(__fadd_rn(__fadd_rn(p0.x, p1.x), p2.x), 3.0f), 255.0f);
                int g1 = (int)__fmul_rn(__fdiv_rn(__fadd_rn(__fadd_rn(p0.y, p1.y), p2.y), 3.0f), 255.0f);
                int g2 = (int)__fmul_rn(__fdiv_rn(__fadd_rn(__fadd_rn(p0.z, p1.z), p2.z), 3.0f), 255.0f);
                int g3 = (int)__fmul_rn(__fdiv_rn(__fadd_rn(__fadd_rn(p0.w, p1.w), p2.w), 3.0f), 255.0f);
                s += (unsigned)(g0 + g1 + g2 + g3);
                q += (unsigned)(g0 * g0 + g1 * g1 + g2 * g2 + g3 * g3);
                gw[widx] = (unsigned)g0 | ((unsigned)g1 << 8) | ((unsigned)g2 << 16) | ((unsigned)g3 << 24);
            }
        }
        // exact u32 block reduction, then one deterministic atomic per item
        s = __reduce_add_sync(0xFFFFFFFFu, s);
        q = __reduce_add_sync(0xFFFFFFFFu, q);
        const int warp = threadIdx.x >> 5, lane = threadIdx.x & 31;
        if (lane == 0) { ss[warp] = s; sq[warp] = q; }
        __syncthreads();
        if (threadIdx.x == 0) {
            unsigned int ts = 0, tq = 0;
            #pragma unroll
            for (int i = 0; i < 8; i++) { ts += ss[i]; tq += sq[i]; }
            atomicAdd(&d_sum[n], ts);
            atomicAdd(&d_sumsq[n], tq);
        }
        __syncthreads();
    }
}

// ---------------- Kernel 2: per-(image,offset) GLCM, u8 smem histogram ----------------
// 32 pairs per iteration; poison padding removes all edge predicates.
template <int DR, int DC>
__device__ __forceinline__ void glcm_body(int n, int out_idx, unsigned int* hist) {
    constexpr int A0 = (DC < 0) ? 1 : 0;     // a-column shift
    constexpr int B0 = (DC > 0) ? 1 : 0;     // b-column shift
    constexpr int R  = H - DR;
    constexpr int C2 = W - ((DC < 0) ? -DC : DC);
    constexpr float NP = (float)(R * C2);

    const uint4* __restrict__ g4 = g_buf4 + (size_t)n * (224 * V4PR);
    const int tid = threadIdx.x;

    // zero 64 KB histogram
    {
        uint4 z = make_uint4(0u, 0u, 0u, 0u);
        uint4* h4 = (uint4*)hist;
        #pragma unroll
        for (int i = tid; i < HIST_WORDS / 4; i += K2_THREADS) h4[i] = z;
    }
    __syncthreads();

    // ---- pair accumulation: 32 pairs/iter, zero edge handling ----
    const int total = R * 7;                 // 7 chunks of 32 columns per row
    for (int m = tid; m < total; m += K2_THREADS) {
        const int r = m / 7;
        const int k = m - r * 7;
        const uint4* rowa = g4 + r * V4PR;
        const uint4* rowb = g4 + (r + DR) * V4PR;
        uint4 av0 = rowa[k * 2], av1 = rowa[k * 2 + 1];
        uint4 bv0 = rowb[k * 2], bv1 = rowb[k * 2 + 1];
        unsigned int A[9] = { av0.x, av0.y, av0.z, av0.w, av1.x, av1.y, av1.z, av1.w, 0u };
        unsigned int B[9] = { bv0.x, bv0.y, bv0.z, bv0.w, bv1.x, bv1.y, bv1.z, bv1.w, 0u };
        if (A0) A[8] = ((const unsigned int*)rowa)[k * 8 + 8];  // k=6 -> poison pad word
        if (B0) B[8] = ((const unsigned int*)rowb)[k * 8 + 8];
        #pragma unroll
        for (int w = 0; w < 8; w++) {
            const unsigned int awv = A0 ? __funnelshift_r(A[w], A[w + 1], 8) : A[w];
            const unsigned int bwv = B0 ? __funnelshift_r(B[w], B[w + 1], 8) : B[w];
            #pragma unroll
            for (int p = 0; p < 4; p++) {
                unsigned int a = __byte_perm(awv, 0u, 0x4440u + (unsigned)p);
                unsigned int b = __byte_perm(bwv, 0u, 0x4440u + (unsigned)p);
                // swizzled u8 bin layout: slot(i,j) = i*256 + ((j + 4i) & 255)
                unsigned int t = b + 4u * a;
                unsigned int woff = (a << 8) | (t & 252u);        // byte offset of u32 word
                unsigned int val = __funnelshift_l(0u, 1u, b << 3); // 1 << (8*(b&3))
                atomicAdd((unsigned int*)((char*)hist + woff), val);
            }
        }
    }
    __syncthreads();

    // ---- stats over 64K bins (exclude poison row/col 255) ----
    float s2 = 0.f, scon = 0.f, sdis = 0.f, shom = 0.f;
    #pragma unroll 4
    for (int it = 0; it < 65536 / K2_THREADS; ++it) {
        const int l = tid + it * K2_THREADS;
        const int i = l >> 8, j = l & 255;
        const unsigned int slot1 = (unsigned)((i << 8) | ((j + 4 * i) & 255));
        const unsigned int c1 = (hist[slot1 >> 2] >> ((slot1 & 3u) << 3)) & 255u;
        const unsigned int slot2 = (unsigned)((j << 8) | ((i + 4 * j) & 255));
        const unsigned int c2 = (hist[slot2 >> 2] >> ((slot2 & 3u) << 3)) & 255u;
        const float vm = (i < 255 && j < 255) ? 1.0f : 0.0f;   // poison-bin mask
        const float cs = (float)(c1 + c2) * vm;
        s2 += cs * cs;
        const float d  = (float)(i - j);
        const float d2 = d * d;
        const float cf = (float)c1 * vm;
        scon += cf * d2;
        sdis += cf * fabsf(d);
        shom += cf / (1.0f + d2);
    }

    // deterministic block reduction (16 warps)
    __shared__ float red[4][16];
    float v0 = s2, v1 = scon, v2 = sdis, v3 = shom;
    #pragma unroll
    for (int off = 16; off; off >>= 1) {
        v0 += __shfl_xor_sync(0xFFFFFFFFu, v0, off);
        v1 += __shfl_xor_sync(0xFFFFFFFFu, v1, off);
        v2 += __shfl_xor_sync(0xFFFFFFFFu, v2, off);
        v3 += __shfl_xor_sync(0xFFFFFFFFu, v3, off);
    }
    const int warp = tid >> 5, lane = tid & 31;
    if (lane == 0) { red[0][warp] = v0; red[1][warp] = v1; red[2][warp] = v2; red[3][warp] = v3; }
    __syncthreads();
    if (tid < 16) {
        float a0 = red[0][tid], a1 = red[1][tid], a2 = red[2][tid], a3 = red[3][tid];
        #pragma unroll
        for (int off = 8; off; off >>= 1) {
            a0 += __shfl_xor_sync(0xFFFFu, a0, off);
            a1 += __shfl_xor_sync(0xFFFFu, a1, off);
            a2 += __shfl_xor_sync(0xFFFFu, a2, off);
            a3 += __shfl_xor_sync(0xFFFFu, a3, off);
        }
        if (tid == 0) {
            d_feat[out_idx * 4 + 0] = a1 / NP;                   // contrast
            d_feat[out_idx * 4 + 1] = a2 / NP;                   // dissimilarity
            d_feat[out_idx * 4 + 2] = a3 / NP;                   // homogeneity
            d_feat[out_idx * 4 + 3] = a0 / (4.0f * NP * NP);     // ASM
        }
    }
}

__global__ __launch_bounds__(K2_THREADS, 2) void glcm_kernel() {
    extern __shared__ unsigned int hist[];
    const int bx = blockIdx.x;
    const int n = bx >> 2;
    const int o = bx & 3;
    switch (o) {
        case 0: glcm_body<0, 1>(n, bx, hist); break;   // (0,1)
        case 1: glcm_body<1, 1>(n, bx, hist); break;   // (1,1)
        case 2: glcm_body<1, 0>(n, bx, hist); break;   // (1,0)
        default: glcm_body<1, -1>(n, bx, hist); break; // (1,-1)
    }
}

// ---------------- Kernel 3: finalize (also resets moment accumulators) ----------------
__global__ __launch_bounds__(256) void finalize_kernel(float* __restrict__ out) {
    const int n = threadIdx.x;
    const unsigned int tsum = d_sum[n];
    const unsigned int tsq  = d_sumsq[n];
    d_sum[n] = 0u;            // self-clean for next graph replay
    d_sumsq[n] = 0u;
    const double inv = 1.0 / (double)NPIX;
    const double mean = (double)tsum * inv;
    double var = (double)tsq * inv - mean * mean;
    if (var < 0.0) var = 0.0;
    float con = 0.f, dis = 0.f, hom = 0.f, as = 0.f;
    #pragma unroll
    for (int o = 0; o < 4; o++) {
        const float* f4 = &d_feat[(n * 4 + o) * 4];
        con += f4[0]; dis += f4[1]; hom += f4[2]; as += f4[3];
    }
    con *= 0.25f; dis *= 0.25f; hom *= 0.25f; as *= 0.25f;
    float* o6 = out + n * 6;
    o6[0] = (float)sqrt(var);
    o6[1] = con;
    o6[2] = dis;
    o6[3] = hom;
    o6[4] = as;
    o6[5] = sqrtf(as);
}

// ---------------- launch ----------------
extern "C" void kernel_launch(void* const* d_in, const int* in_sizes, int n_in,
                              void* d_out, int out_size) {
    (void)in_sizes; (void)n_in; (void)out_size;
    const float* x = (const float*)d_in[0];
    float* out = (float*)d_out;

    cudaFuncSetAttribute(glcm_kernel, cudaFuncAttributeMaxDynamicSharedMemorySize,
                         HIST_WORDS * sizeof(unsigned int));

    quantize_kernel<<<1184, 256>>>(x);
    glcm_kernel<<<K2_BLOCKS, K2_THREADS, HIST_WORDS * sizeof(unsigned int)>>>();
    finalize_kernel<<<1, NIMG>>>(out);
}

// round 11
// speedup vs baseline: 1.4317x; 1.0279x over previous
#include <cuda_runtime.h>
#include <cstdint>

#define H 224
#define W 224
#define NPIX (H * W)          // 50176
#define NIMG 256
#define WPR 60                // words per padded row (56 data + 4 pad)
#define V4PR 15               // uint4 per padded row
#define K2_THREADS 512
#define K2_BLOCKS (NIMG * 4)
#define HIST_WORDS 16384      // 65536 u8 bins packed 4-per-u32 = 64 KB

// ---------------- scratch (no allocations allowed) ----------------
__device__ uint4         g_buf4[(size_t)NIMG * 224 * V4PR];   // padded gray images
__device__ unsigned int  d_sum8[NIMG * 8];
__device__ unsigned int  d_sumsq8[NIMG * 8];
__device__ float         d_feat[NIMG * 4 * 4];   // [n][offset][con,dis,hom,asm]

// ---------------- Kernel 1: quantize + moments (8 CTAs per image) ----------------
// Branch-free hot loop; padded output via pv = v + 4*(v/56); pads in a mini-loop.
__global__ __launch_bounds__(256) void quantize_kernel(const float* __restrict__ x) {
    const int n = blockIdx.x >> 3;       // image index = b*16 + f
    const int q = blockIdx.x & 7;        // eighth
    const int b = n >> 4, f = n & 15;
    const float4* __restrict__ xb = (const float4*)x + (size_t)(b * 48 + f) * 12544;
    unsigned int* __restrict__ gw = (unsigned int*)g_buf4 + (size_t)n * (224 * WPR);

    const int v0 = q * 1568;             // 12544 data words / 8
    const int v1 = v0 + 1568;

    unsigned int s = 0, qq = 0;
    for (int v = v0 + threadIdx.x; v < v1; v += 256) {
        float4 p0 = xb[v];
        float4 p1 = xb[v + 16 * 12544];
        float4 p2 = xb[v + 32 * 12544];
        // match jnp.mean -> sum/3, then *255, floor (no FMA/reassociation)
        int g0 = (int)__fmul_rn(__fdiv_rn(__fadd_rn(__fadd_rn(p0.x, p1.x), p2.x), 3.0f), 255.0f);
        int g1 = (int)__fmul_rn(__fdiv_rn(__fadd_rn(__fadd_rn(p0.y, p1.y), p2.y), 3.0f), 255.0f);
        int g2 = (int)__fmul_rn(__fdiv_rn(__fadd_rn(__fadd_rn(p0.z, p1.z), p2.z), 3.0f), 255.0f);
        int g3 = (int)__fmul_rn(__fdiv_rn(__fadd_rn(__fadd_rn(p0.w, p1.w), p2.w), 3.0f), 255.0f);
        s  += (unsigned)(g0 + g1 + g2 + g3);
        qq += (unsigned)(g0 * g0 + g1 * g1 + g2 * g2 + g3 * g3);
        const int pv = v + 4 * (v / 56);     // padded-layout word index
        gw[pv] = (unsigned)g0 | ((unsigned)g1 << 8) | ((unsigned)g2 << 16) | ((unsigned)g3 << 24);
    }

    // poison pads for this eighth's 28 rows (bin 255 never occurs naturally)
    {
        const int rbase = q * 28;
        if (threadIdx.x < 112) {
            const int row = rbase + (threadIdx.x >> 2);
            gw[row * WPR + 56 + (threadIdx.x & 3)] = 0xFFFFFFFFu;
        }
    }

    // exact u32 block reduction, one deterministic store per item
    s  = __reduce_add_sync(0xFFFFFFFFu, s);
    qq = __reduce_add_sync(0xFFFFFFFFu, qq);
    __shared__ unsigned int ss[8], sq[8];
    const int warp = threadIdx.x >> 5, lane = threadIdx.x & 31;
    if (lane == 0) { ss[warp] = s; sq[warp] = qq; }
    __syncthreads();
    if (threadIdx.x == 0) {
        unsigned int ts = 0, tq = 0;
        #pragma unroll
        for (int i = 0; i < 8; i++) { ts += ss[i]; tq += sq[i]; }
        d_sum8[blockIdx.x] = ts; d_sumsq8[blockIdx.x] = tq;
    }
}

// ---------------- Kernel 2: per-(image,offset) GLCM, u8 smem histogram ----------------
// 32 pairs per iteration; poison padding removes all edge predicates.
template <int DR, int DC>
__device__ __forceinline__ void glcm_body(int n, int out_idx, unsigned int* hist) {
    constexpr int A0 = (DC < 0) ? 1 : 0;     // a-column shift
    constexpr int B0 = (DC > 0) ? 1 : 0;     // b-column shift
    constexpr int R  = H - DR;
    constexpr int C2 = W - ((DC < 0) ? -DC : DC);
    constexpr float NP = (float)(R * C2);

    const uint4* __restrict__ g4 = g_buf4 + (size_t)n * (224 * V4PR);
    const int tid = threadIdx.x;

    // zero 64 KB histogram
    {
        uint4 z = make_uint4(0u, 0u, 0u, 0u);
        uint4* h4 = (uint4*)hist;
        #pragma unroll
        for (int i = tid; i < HIST_WORDS / 4; i += K2_THREADS) h4[i] = z;
    }
    __syncthreads();

    // ---- pair accumulation: 32 pairs/iter, zero edge handling ----
    const int total = R * 7;                 // 7 chunks of 32 columns per row
    for (int m = tid; m < total; m += K2_THREADS) {
        const int r = m / 7;
        const int k = m - r * 7;
        const uint4* rowa = g4 + r * V4PR;
        const uint4* rowb = g4 + (r + DR) * V4PR;
        uint4 av0 = rowa[k * 2], av1 = rowa[k * 2 + 1];
        uint4 bv0 = rowb[k * 2], bv1 = rowb[k * 2 + 1];
        unsigned int A[9] = { av0.x, av0.y, av0.z, av0.w, av1.x, av1.y, av1.z, av1.w, 0u };
        unsigned int B[9] = { bv0.x, bv0.y, bv0.z, bv0.w, bv1.x, bv1.y, bv1.z, bv1.w, 0u };
        if (A0) A[8] = ((const unsigned int*)rowa)[k * 8 + 8];  // k=6 -> poison pad word
        if (B0) B[8] = ((const unsigned int*)rowb)[k * 8 + 8];
        #pragma unroll
        for (int w = 0; w < 8; w++) {
            const unsigned int awv = A0 ? __funnelshift_r(A[w], A[w + 1], 8) : A[w];
            const unsigned int bwv = B0 ? __funnelshift_r(B[w], B[w + 1], 8) : B[w];
            #pragma unroll
            for (int p = 0; p < 4; p++) {
                unsigned int a = __byte_perm(awv, 0u, 0x4440u + (unsigned)p);
                unsigned int b = __byte_perm(bwv, 0u, 0x4440u + (unsigned)p);
                // swizzled u8 bin layout: slot(i,j) = i*256 + ((j + 4i) & 255)
                unsigned int t = b + 4u * a;
                unsigned int woff = (a << 8) | (t & 252u);        // byte offset of u32 word
                unsigned int val = __funnelshift_l(0u, 1u, b << 3); // 1 << (8*(b&3))
                atomicAdd((unsigned int*)((char*)hist + woff), val);
            }
        }
    }
    __syncthreads();

    // ---- stats over 64K bins (exclude poison row/col 255) ----
    float s2 = 0.f, scon = 0.f, sdis = 0.f, shom = 0.f;
    #pragma unroll 4
    for (int it = 0; it < 65536 / K2_THREADS; ++it) {
        const int l = tid + it * K2_THREADS;
        const int i = l >> 8, j = l & 255;
        const unsigned int slot1 = (unsigned)((i << 8) | ((j + 4 * i) & 255));
        const unsigned int c1 = (hist[slot1 >> 2] >> ((slot1 & 3u) << 3)) & 255u;
        const unsigned int slot2 = (unsigned)((j << 8) | ((i + 4 * j) & 255));
        const unsigned int c2 = (hist[slot2 >> 2] >> ((slot2 & 3u) << 3)) & 255u;
        const float vm = (i < 255 && j < 255) ? 1.0f : 0.0f;   // poison-bin mask
        const float cs = (float)(c1 + c2) * vm;
        s2 += cs * cs;
        const float d  = (float)(i - j);
        const float d2 = d * d;
        const float cf = (float)c1 * vm;
        scon += cf * d2;
        sdis += cf * fabsf(d);
        shom += cf / (1.0f + d2);
    }

    // deterministic block reduction (16 warps)
    __shared__ float red[4][16];
    float v0 = s2, v1 = scon, v2 = sdis, v3 = shom;
    #pragma unroll
    for (int off = 16; off; off >>= 1) {
        v0 += __shfl_xor_sync(0xFFFFFFFFu, v0, off);
        v1 += __shfl_xor_sync(0xFFFFFFFFu, v1, off);
        v2 += __shfl_xor_sync(0xFFFFFFFFu, v2, off);
        v3 += __shfl_xor_sync(0xFFFFFFFFu, v3, off);
    }
    const int warp = tid >> 5, lane = tid & 31;
    if (lane == 0) { red[0][warp] = v0; red[1][warp] = v1; red[2][warp] = v2; red[3][warp] = v3; }
    __syncthreads();
    if (tid < 16) {
        float a0 = red[0][tid], a1 = red[1][tid], a2 = red[2][tid], a3 = red[3][tid];
        #pragma unroll
        for (int off = 8; off; off >>= 1) {
            a0 += __shfl_xor_sync(0xFFFFu, a0, off);
            a1 += __shfl_xor_sync(0xFFFFu, a1, off);
            a2 += __shfl_xor_sync(0xFFFFu, a2, off);
            a3 += __shfl_xor_sync(0xFFFFu, a3, off);
        }
        if (tid == 0) {
            d_feat[out_idx * 4 + 0] = a1 / NP;                   // contrast
            d_feat[out_idx * 4 + 1] = a2 / NP;                   // dissimilarity
            d_feat[out_idx * 4 + 2] = a3 / NP;                   // homogeneity
            d_feat[out_idx * 4 + 3] = a0 / (4.0f * NP * NP);     // ASM
        }
    }
}

__global__ __launch_bounds__(K2_THREADS, 2) void glcm_kernel() {
    extern __shared__ unsigned int hist[];
    const int bx = blockIdx.x;
    const int n = bx >> 2;
    const int o = bx & 3;
    switch (o) {
        case 0: glcm_body<0, 1>(n, bx, hist); break;   // (0,1)
        case 1: glcm_body<1, 1>(n, bx, hist); break;   // (1,1)
        case 2: glcm_body<1, 0>(n, bx, hist); break;   // (1,0)
        default: glcm_body<1, -1>(n, bx, hist); break; // (1,-1)
    }
}

// ---------------- Kernel 3: finalize ----------------
__global__ __launch_bounds__(256) void finalize_kernel(float* __restrict__ out) {
    const int n = threadIdx.x;
    unsigned int tsum = 0, tsq = 0;
    #pragma unroll
    for (int q = 0; q < 8; q++) { tsum += d_sum8[n * 8 + q]; tsq += d_sumsq8[n * 8 + q]; }
    const double inv = 1.0 / (double)NPIX;
    const double mean = (double)tsum * inv;
    double var = (double)tsq * inv - mean * mean;
    if (var < 0.0) var = 0.0;
    float con = 0.f, dis = 0.f, hom = 0.f, as = 0.f;
    #pragma unroll
    for (int o = 0; o < 4; o++) {
        const float* f4 = &d_feat[(n * 4 + o) * 4];
        con += f4[0]; dis += f4[1]; hom += f4[2]; as += f4[3];
    }
    con *= 0.25f; dis *= 0.25f; hom *= 0.25f; as *= 0.25f;
    float* o6 = out + n * 6;
    o6[0] = (float)sqrt(var);
    o6[1] = con;
    o6[2] = dis;
    o6[3] = hom;
    o6[4] = as;
    o6[5] = sqrtf(as);
}

// ---------------- launch ----------------
extern "C" void kernel_launch(void* const* d_in, const int* in_sizes, int n_in,
                              void* d_out, int out_size) {
    (void)in_sizes; (void)n_in; (void)out_size;
    const float* x = (const float*)d_in[0];
    float* out = (float*)d_out;

    cudaFuncSetAttribute(glcm_kernel, cudaFuncAttributeMaxDynamicSharedMemorySize,
                         HIST_WORDS * sizeof(unsigned int));

    quantize_kernel<<<NIMG * 8, 256>>>(x);
    glcm_kernel<<<K2_BLOCKS, K2_THREADS, HIST_WORDS * sizeof(unsigned int)>>>();
    finalize_kernel<<<1, NIMG>>>(out);
}

// round 12
// speedup vs baseline: 1.4510x; 1.0135x over previous
#include <cuda_runtime.h>
#include <cstdint>

#define H 224
#define W 224
#define NPIX (H * W)          // 50176
#define NIMG 256
#define WPR 60                // words per padded row (56 data + 4 pad)
#define V4PR 15               // uint4 per padded row
#define K2_THREADS 512
#define K2_BLOCKS (NIMG * 4)
#define HIST_WORDS 16384      // 65536 u8 bins packed 4-per-u32 = 64 KB

// ---------------- scratch (no allocations allowed) ----------------
__device__ uint4         g_buf4[(size_t)NIMG * 224 * V4PR];   // padded gray images
__device__ unsigned int  d_sum8[NIMG * 8];
__device__ unsigned int  d_sumsq8[NIMG * 8];
__device__ float         d_feat[NIMG * 4 * 4];   // [n][offset][con,dis,hom,asm]

// ---------------- Kernel 1: quantize + moments (8 CTAs per image) ----------------
// launch_bounds(256,8): 32-reg cap -> 8 CTAs/SM (full 2048-thread occupancy).
// __ldcs streaming reads: x passes through L2 evict-first, preserving g_buf
// residency for K2's read phase.
__global__ __launch_bounds__(256, 8) void quantize_kernel(const float* __restrict__ x) {
    const int n = blockIdx.x >> 3;       // image index = b*16 + f
    const int q = blockIdx.x & 7;        // eighth
    const int b = n >> 4, f = n & 15;
    const float4* __restrict__ xb = (const float4*)x + (size_t)(b * 48 + f) * 12544;
    unsigned int* __restrict__ gw = (unsigned int*)g_buf4 + (size_t)n * (224 * WPR);

    const int v0 = q * 1568;             // 12544 data words / 8
    const int v1 = v0 + 1568;

    unsigned int s = 0, qq = 0;
    for (int v = v0 + threadIdx.x; v < v1; v += 256) {
        float4 p0 = __ldcs(&xb[v]);
        float4 p1 = __ldcs(&xb[v + 16 * 12544]);
        float4 p2 = __ldcs(&xb[v + 32 * 12544]);
        // match jnp.mean -> sum/3, then *255, floor (no FMA/reassociation)
        int g0 = (int)__fmul_rn(__fdiv_rn(__fadd_rn(__fadd_rn(p0.x, p1.x), p2.x), 3.0f), 255.0f);
        int g1 = (int)__fmul_rn(__fdiv_rn(__fadd_rn(__fadd_rn(p0.y, p1.y), p2.y), 3.0f), 255.0f);
        int g2 = (int)__fmul_rn(__fdiv_rn(__fadd_rn(__fadd_rn(p0.z, p1.z), p2.z), 3.0f), 255.0f);
        int g3 = (int)__fmul_rn(__fdiv_rn(__fadd_rn(__fadd_rn(p0.w, p1.w), p2.w), 3.0f), 255.0f);
        s  += (unsigned)(g0 + g1 + g2 + g3);
        qq += (unsigned)(g0 * g0 + g1 * g1 + g2 * g2 + g3 * g3);
        const int pv = v + 4 * (v / 56);     // padded-layout word index
        gw[pv] = (unsigned)g0 | ((unsigned)g1 << 8) | ((unsigned)g2 << 16) | ((unsigned)g3 << 24);
    }

    // poison pads for this eighth's 28 rows (bin 255 never occurs naturally)
    {
        const int rbase = q * 28;
        if (threadIdx.x < 112) {
            const int row = rbase + (threadIdx.x >> 2);
            gw[row * WPR + 56 + (threadIdx.x & 3)] = 0xFFFFFFFFu;
        }
    }

    // exact u32 block reduction, one deterministic store per item
    s  = __reduce_add_sync(0xFFFFFFFFu, s);
    qq = __reduce_add_sync(0xFFFFFFFFu, qq);
    __shared__ unsigned int ss[8], sq[8];
    const int warp = threadIdx.x >> 5, lane = threadIdx.x & 31;
    if (lane == 0) { ss[warp] = s; sq[warp] = qq; }
    __syncthreads();
    if (threadIdx.x == 0) {
        unsigned int ts = 0, tq = 0;
        #pragma unroll
        for (int i = 0; i < 8; i++) { ts += ss[i]; tq += sq[i]; }
        d_sum8[blockIdx.x] = ts; d_sumsq8[blockIdx.x] = tq;
    }
}

// ---------------- Kernel 2: per-(image,offset) GLCM, u8 smem histogram ----------------
// 32 pairs per iteration; poison padding removes all edge predicates.
// At the measured ATOMS lane ceiling (1/cyc/SM) -- do not modify.
template <int DR, int DC>
__device__ __forceinline__ void glcm_body(int n, int out_idx, unsigned int* hist) {
    constexpr int A0 = (DC < 0) ? 1 : 0;     // a-column shift
    constexpr int B0 = (DC > 0) ? 1 : 0;     // b-column shift
    constexpr int R  = H - DR;
    constexpr int C2 = W - ((DC < 0) ? -DC : DC);
    constexpr float NP = (float)(R * C2);

    const uint4* __restrict__ g4 = g_buf4 + (size_t)n * (224 * V4PR);
    const int tid = threadIdx.x;

    // zero 64 KB histogram
    {
        uint4 z = make_uint4(0u, 0u, 0u, 0u);
        uint4* h4 = (uint4*)hist;
        #pragma unroll
        for (int i = tid; i < HIST_WORDS / 4; i += K2_THREADS) h4[i] = z;
    }
    __syncthreads();

    // ---- pair accumulation: 32 pairs/iter, zero edge handling ----
    const int total = R * 7;                 // 7 chunks of 32 columns per row
    for (int m = tid; m < total; m += K2_THREADS) {
        const int r = m / 7;
        const int k = m - r * 7;
        const uint4* rowa = g4 + r * V4PR;
        const uint4* rowb = g4 + (r + DR) * V4PR;
        uint4 av0 = rowa[k * 2], av1 = rowa[k * 2 + 1];
        uint4 bv0 = rowb[k * 2], bv1 = rowb[k * 2 + 1];
        unsigned int A[9] = { av0.x, av0.y, av0.z, av0.w, av1.x, av1.y, av1.z, av1.w, 0u };
        unsigned int B[9] = { bv0.x, bv0.y, bv0.z, bv0.w, bv1.x, bv1.y, bv1.z, bv1.w, 0u };
        if (A0) A[8] = ((const unsigned int*)rowa)[k * 8 + 8];  // k=6 -> poison pad word
        if (B0) B[8] = ((const unsigned int*)rowb)[k * 8 + 8];
        #pragma unroll
        for (int w = 0; w < 8; w++) {
            const unsigned int awv = A0 ? __funnelshift_r(A[w], A[w + 1], 8) : A[w];
            const unsigned int bwv = B0 ? __funnelshift_r(B[w], B[w + 1], 8) : B[w];
            #pragma unroll
            for (int p = 0; p < 4; p++) {
                unsigned int a = __byte_perm(awv, 0u, 0x4440u + (unsigned)p);
                unsigned int b = __byte_perm(bwv, 0u, 0x4440u + (unsigned)p);
                // swizzled u8 bin layout: slot(i,j) = i*256 + ((j + 4i) & 255)
                unsigned int t = b + 4u * a;
                unsigned int woff = (a << 8) | (t & 252u);        // byte offset of u32 word
                unsigned int val = __funnelshift_l(0u, 1u, b << 3); // 1 << (8*(b&3))
                atomicAdd((unsigned int*)((char*)hist + woff), val);
            }
        }
    }
    __syncthreads();

    // ---- stats over 64K bins (exclude poison row/col 255) ----
    float s2 = 0.f, scon = 0.f, sdis = 0.f, shom = 0.f;
    #pragma unroll 4
    for (int it = 0; it < 65536 / K2_THREADS; ++it) {
        const int l = tid + it * K2_THREADS;
        const int i = l >> 8, j = l & 255;
        const unsigned int slot1 = (unsigned)((i << 8) | ((j + 4 * i) & 255));
        const unsigned int c1 = (hist[slot1 >> 2] >> ((slot1 & 3u) << 3)) & 255u;
        const unsigned int slot2 = (unsigned)((j << 8) | ((i + 4 * j) & 255));
        const unsigned int c2 = (hist[slot2 >> 2] >> ((slot2 & 3u) << 3)) & 255u;
        const float vm = (i < 255 && j < 255) ? 1.0f : 0.0f;   // poison-bin mask
        const float cs = (float)(c1 + c2) * vm;
        s2 += cs * cs;
        const float d  = (float)(i - j);
        const float d2 = d * d;
        const float cf = (float)c1 * vm;
        scon += cf * d2;
        sdis += cf * fabsf(d);
        shom += cf / (1.0f + d2);
    }

    // deterministic block reduction (16 warps)
    __shared__ float red[4][16];
    float v0 = s2, v1 = scon, v2 = sdis, v3 = shom;
    #pragma unroll
    for (int off = 16; off; off >>= 1) {
        v0 += __shfl_xor_sync(0xFFFFFFFFu, v0, off);
        v1 += __shfl_xor_sync(0xFFFFFFFFu, v1, off);
        v2 += __shfl_xor_sync(0xFFFFFFFFu, v2, off);
        v3 += __shfl_xor_sync(0xFFFFFFFFu, v3, off);
    }
    const int warp = tid >> 5, lane = tid & 31;
    if (lane == 0) { red[0][warp] = v0; red[1][warp] = v1; red[2][warp] = v2; red[3][warp] = v3; }
    __syncthreads();
    if (tid < 16) {
        float a0 = red[0][tid], a1 = red[1][tid], a2 = red[2][tid], a3 = red[3][tid];
        #pragma unroll
        for (int off = 8; off; off >>= 1) {
            a0 += __shfl_xor_sync(0xFFFFu, a0, off);
            a1 += __shfl_xor_sync(0xFFFFu, a1, off);
            a2 += __shfl_xor_sync(0xFFFFu, a2, off);
            a3 += __shfl_xor_sync(0xFFFFu, a3, off);
        }
        if (tid == 0) {
            d_feat[out_idx * 4 + 0] = a1 / NP;                   // contrast
            d_feat[out_idx * 4 + 1] = a2 / NP;                   // dissimilarity
            d_feat[out_idx * 4 + 2] = a3 / NP;                   // homogeneity
            d_feat[out_idx * 4 + 3] = a0 / (4.0f * NP * NP);     // ASM
        }
    }
}

__global__ __launch_bounds__(K2_THREADS, 2) void glcm_kernel() {
    extern __shared__ unsigned int hist[];
    const int bx = blockIdx.x;
    const int n = bx >> 2;
    const int o = bx & 3;
    switch (o) {
        case 0: glcm_body<0, 1>(n, bx, hist); break;   // (0,1)
        case 1: glcm_body<1, 1>(n, bx, hist); break;   // (1,1)
        case 2: glcm_body<1, 0>(n, bx, hist); break;   // (1,0)
        default: glcm_body<1, -1>(n, bx, hist); break; // (1,-1)
    }
}

// ---------------- Kernel 3: finalize ----------------
__global__ __launch_bounds__(256) void finalize_kernel(float* __restrict__ out) {
    const int n = threadIdx.x;
    unsigned int tsum = 0, tsq = 0;
    #pragma unroll
    for (int q = 0; q < 8; q++) { tsum += d_sum8[n * 8 + q]; tsq += d_sumsq8[n * 8 + q]; }
    const double inv = 1.0 / (double)NPIX;
    const double mean = (double)tsum * inv;
    double var = (double)tsq * inv - mean * mean;
    if (var < 0.0) var = 0.0;
    float con = 0.f, dis = 0.f, hom = 0.f, as = 0.f;
    #pragma unroll
    for (int o = 0; o < 4; o++) {
        const float* f4 = &d_feat[(n * 4 + o) * 4];
        con += f4[0]; dis += f4[1]; hom += f4[2]; as += f4[3];
    }
    con *= 0.25f; dis *= 0.25f; hom *= 0.25f; as *= 0.25f;
    float* o6 = out + n * 6;
    o6[0] = (float)sqrt(var);
    o6[1] = con;
    o6[2] = dis;
    o6[3] = hom;
    o6[4] = as;
    o6[5] = sqrtf(as);
}

// ---------------- launch ----------------
extern "C" void kernel_launch(void* const* d_in, const int* in_sizes, int n_in,
                              void* d_out, int out_size) {
    (void)in_sizes; (void)n_in; (void)out_size;
    const float* x = (const float*)d_in[0];
    float* out = (float*)d_out;

    cudaFuncSetAttribute(glcm_kernel, cudaFuncAttributeMaxDynamicSharedMemorySize,
                         HIST_WORDS * sizeof(unsigned int));

    quantize_kernel<<<NIMG * 8, 256>>>(x);
    glcm_kernel<<<K2_BLOCKS, K2_THREADS, HIST_WORDS * sizeof(unsigned int)>>>();
    finalize_kernel<<<1, NIMG>>>(out);
}